// round 6
// baseline (speedup 1.0000x reference)
#include <cuda_runtime.h>
#include <cstdint>
#include <math.h>

// Problem constants (fixed shapes from reference)
#define NN 50000
#define EE 800000
#define ET (EE + NN)   // edges + self loops
#define INCH 128
#define HID 64
#define H1 4
#define OUT 64
#define F1 (H1*HID)    // 256

// ---------------- scratch (device globals; no allocation allowed) ----------
__device__ __align__(16) float g_h1[(size_t)NN * F1];     // x @ W1
__device__ __align__(16) float g_out1[(size_t)NN * F1];   // layer1 agg (+b1, ELU in place)
__device__ __align__(16) float g_h2[(size_t)NN * OUT];    // elu_out @ W2
__device__ __align__(16) float g_als1[NN * H1];
__device__ __align__(16) float g_ald1[NN * H1];
__device__ __align__(16) float g_mx1[NN * H1];
__device__ __align__(16) float g_dn1[NN * H1];
__device__ __align__(16) float g_lg1[(size_t)ET * H1];    // logits, then exp (in place)
__device__ __align__(16) float g_als2[NN];
__device__ __align__(16) float g_ald2[NN];
__device__ __align__(16) float g_mx2[NN];
__device__ __align__(16) float g_dn2[NN];
__device__ __align__(16) float g_lg2[ET];
// decoded edge indices (int32, self-loops appended)
__device__ int g_src[ET];
__device__ int g_dst[ET];
__device__ int g_is64;

// ---------------- helpers ----------------
__device__ __forceinline__ void red_add4(float* p, float x, float y, float z, float w) {
    asm volatile("red.global.add.v4.f32 [%0], {%1, %2, %3, %4};"
                 :: "l"(p), "f"(x), "f"(y), "f"(z), "f"(w) : "memory");
}

__device__ __forceinline__ void atomicMaxF(float* addr, float v) {
    if (v >= 0.0f) atomicMax((int*)addr, __float_as_int(v));
    else           atomicMin((unsigned int*)addr, __float_as_uint(v));
}

__device__ __forceinline__ float lrelu(float x) { return x > 0.0f ? x : 0.2f * x; }

#define NEG_INF __int_as_float(0xff800000)

// ---------------- edge index dtype detection + conversion ----------------
// If edge_index is int64 with values < 50000, every high 32-bit word is 0.
// If it is int32, "high words" are random indices in [0, 50000) — the chance
// that 64 of them are all zero is ~0.  One thread decides; convert kernel
// branches uniformly on the flag.
__global__ void k_detect(const int* __restrict__ ei_raw) {
    if (blockIdx.x == 0 && threadIdx.x == 0) {
        int all0 = 1;
#pragma unroll
        for (int i = 1; i < 128; i += 2) all0 &= (ei_raw[i] == 0);
        g_is64 = all0;
    }
}

__global__ void k_convert(const int* __restrict__ ei_raw) {
    int e = blockIdx.x * blockDim.x + threadIdx.x;
    if (e >= ET) return;
    int s, d;
    if (e < EE) {
        if (g_is64) {
            const long long* p = (const long long*)ei_raw;
            s = (int)p[e]; d = (int)p[EE + e];
        } else {
            s = ei_raw[e]; d = ei_raw[EE + e];
        }
        // safety clamp: a wrong dtype guess degrades to rel_err, not a fault
        s = min(max(s, 0), NN - 1);
        d = min(max(d, 0), NN - 1);
    } else {
        s = d = e - EE;
    }
    g_src[e] = s; g_dst[e] = d;
}

// ---------------- GEMM (fp32 SIMT, register tiled) ----------------
template<int BM, int BN, int BK, int TM, int TN>
__global__ void gemm_kernel(const float* __restrict__ A, const float* __restrict__ B,
                            float* __restrict__ C, int M, int N, int K) {
    __shared__ float As[BK][BM];
    __shared__ float Bs[BK][BN];
    constexpr int THREADS = (BM / TM) * (BN / TN);
    const int tid = threadIdx.x;
    const int tcol = tid % (BN / TN);
    const int trow = tid / (BN / TN);
    const int brow = blockIdx.y * BM;
    const int bcol = blockIdx.x * BN;

    float acc[TM][TN];
#pragma unroll
    for (int i = 0; i < TM; i++)
#pragma unroll
        for (int j = 0; j < TN; j++) acc[i][j] = 0.0f;

    for (int k0 = 0; k0 < K; k0 += BK) {
#pragma unroll
        for (int i = tid * 4; i < BM * BK; i += THREADS * 4) {
            int m = i / BK, kk = i % BK;
            float4 v = make_float4(0.f, 0.f, 0.f, 0.f);
            int gm = brow + m;
            if (gm < M) v = *(const float4*)&A[(size_t)gm * K + k0 + kk];
            As[kk + 0][m] = v.x; As[kk + 1][m] = v.y;
            As[kk + 2][m] = v.z; As[kk + 3][m] = v.w;
        }
#pragma unroll
        for (int i = tid * 4; i < BK * BN; i += THREADS * 4) {
            int kk = i / BN, n = i % BN;
            float4 v = *(const float4*)&B[(size_t)(k0 + kk) * N + bcol + n];
            *(float4*)&Bs[kk][n] = v;
        }
        __syncthreads();
#pragma unroll
        for (int kk = 0; kk < BK; kk++) {
            float ar[TM], br[TN];
#pragma unroll
            for (int i = 0; i < TM; i++) ar[i] = As[kk][trow * TM + i];
#pragma unroll
            for (int j = 0; j < TN; j++) br[j] = Bs[kk][tcol * TN + j];
#pragma unroll
            for (int i = 0; i < TM; i++)
#pragma unroll
                for (int j = 0; j < TN; j++) acc[i][j] += ar[i] * br[j];
        }
        __syncthreads();
    }
#pragma unroll
    for (int i = 0; i < TM; i++) {
        int gm = brow + trow * TM + i;
        if (gm >= M) continue;
#pragma unroll
        for (int j = 0; j < TN; j += 4) {
            float4 v = make_float4(acc[i][j], acc[i][j+1], acc[i][j+2], acc[i][j+3]);
            *(float4*)&C[(size_t)gm * N + bcol + tcol * TN + j] = v;
        }
    }
}

// ---------------- layer 1 kernels ----------------
__global__ void k_init1(const float* __restrict__ b1) {
    int i = blockIdx.x * blockDim.x + threadIdx.x;
    if (i < NN * F1) g_out1[i] = b1[i & (F1 - 1)];
    if (i < NN * H1) { g_mx1[i] = NEG_INF; g_dn1[i] = 0.0f; }
}

__global__ void k_al1(const float* __restrict__ asrc, const float* __restrict__ adst) {
    int t = blockIdx.x * blockDim.x + threadIdx.x;   // node*4 + head
    if (t >= NN * H1) return;
    int n = t >> 2, h = t & 3;
    const float* hp = &g_h1[(size_t)n * F1 + h * HID];
    const float* ap = &asrc[h * HID];
    const float* bp = &adst[h * HID];
    float s = 0.f, d = 0.f;
#pragma unroll
    for (int i = 0; i < HID / 4; i++) {
        float4 hv = *(const float4*)&hp[i * 4];
        float4 av = *(const float4*)&ap[i * 4];
        float4 bv = *(const float4*)&bp[i * 4];
        s += hv.x * av.x + hv.y * av.y + hv.z * av.z + hv.w * av.w;
        d += hv.x * bv.x + hv.y * bv.y + hv.z * bv.z + hv.w * bv.w;
    }
    g_als1[t] = s; g_ald1[t] = d;
}

__global__ void k_logit1() {
    int e = blockIdx.x * blockDim.x + threadIdx.x;
    if (e >= ET) return;
    int s = g_src[e], d = g_dst[e];
    float4 as4 = *(const float4*)&g_als1[s * 4];
    float4 ad4 = *(const float4*)&g_ald1[d * 4];
    float l0 = lrelu(as4.x + ad4.x);
    float l1 = lrelu(as4.y + ad4.y);
    float l2 = lrelu(as4.z + ad4.z);
    float l3 = lrelu(as4.w + ad4.w);
    *(float4*)&g_lg1[(size_t)e * 4] = make_float4(l0, l1, l2, l3);
    atomicMaxF(&g_mx1[d * 4 + 0], l0);
    atomicMaxF(&g_mx1[d * 4 + 1], l1);
    atomicMaxF(&g_mx1[d * 4 + 2], l2);
    atomicMaxF(&g_mx1[d * 4 + 3], l3);
}

__global__ void k_exp1() {
    int e = blockIdx.x * blockDim.x + threadIdx.x;
    if (e >= ET) return;
    int d = g_dst[e];
    float4 l = *(const float4*)&g_lg1[(size_t)e * 4];
    float4 m = *(const float4*)&g_mx1[d * 4];
    float e0 = expf(l.x - m.x);
    float e1 = expf(l.y - m.y);
    float e2 = expf(l.z - m.z);
    float e3 = expf(l.w - m.w);
    *(float4*)&g_lg1[(size_t)e * 4] = make_float4(e0, e1, e2, e3);
    red_add4(&g_dn1[d * 4], e0, e1, e2, e3);
}

__global__ void k_agg1() {
    int gw = (blockIdx.x * blockDim.x + threadIdx.x) >> 5;
    if (gw >= ET) return;
    int lane = threadIdx.x & 31;
    int s = g_src[gw], d = g_dst[gw];
    float4 ev = *(const float4*)&g_lg1[(size_t)gw * 4];
    float4 dn = *(const float4*)&g_dn1[d * 4];
    float alpha[4];
    alpha[0] = ev.x / fmaxf(dn.x, 1e-16f);
    alpha[1] = ev.y / fmaxf(dn.y, 1e-16f);
    alpha[2] = ev.z / fmaxf(dn.z, 1e-16f);
    alpha[3] = ev.w / fmaxf(dn.w, 1e-16f);
    const float* hrow = &g_h1[(size_t)s * F1];
    float* orow = &g_out1[(size_t)d * F1];
#pragma unroll
    for (int r = 0; r < 2; r++) {
        int f4 = lane + r * 32;          // float4 index within the 256-float row
        float al = alpha[f4 >> 4];       // 16 float4 per head
        float4 v = *(const float4*)&hrow[f4 * 4];
        red_add4(&orow[f4 * 4], v.x * al, v.y * al, v.z * al, v.w * al);
    }
}

__global__ void k_elu() {
    int i = blockIdx.x * blockDim.x + threadIdx.x;
    if (i >= NN * F1) return;
    float v = g_out1[i];
    g_out1[i] = v > 0.0f ? v : expm1f(v);
}

// ---------------- layer 2 kernels ----------------
__global__ void k_init2(const float* __restrict__ b2, float* __restrict__ out) {
    int i = blockIdx.x * blockDim.x + threadIdx.x;
    if (i < NN * OUT) out[i] = b2[i & (OUT - 1)];
    if (i < NN) { g_mx2[i] = NEG_INF; g_dn2[i] = 0.0f; }
}

__global__ void k_al2(const float* __restrict__ asrc, const float* __restrict__ adst) {
    int n = blockIdx.x * blockDim.x + threadIdx.x;
    if (n >= NN) return;
    const float* hp = &g_h2[(size_t)n * OUT];
    float s = 0.f, d = 0.f;
#pragma unroll
    for (int i = 0; i < OUT / 4; i++) {
        float4 hv = *(const float4*)&hp[i * 4];
        float4 av = *(const float4*)&asrc[i * 4];
        float4 bv = *(const float4*)&adst[i * 4];
        s += hv.x * av.x + hv.y * av.y + hv.z * av.z + hv.w * av.w;
        d += hv.x * bv.x + hv.y * bv.y + hv.z * bv.z + hv.w * bv.w;
    }
    g_als2[n] = s; g_ald2[n] = d;
}

__global__ void k_logit2() {
    int e = blockIdx.x * blockDim.x + threadIdx.x;
    if (e >= ET) return;
    int s = g_src[e], d = g_dst[e];
    float l = lrelu(g_als2[s] + g_ald2[d]);
    g_lg2[e] = l;
    atomicMaxF(&g_mx2[d], l);
}

__global__ void k_exp2() {
    int e = blockIdx.x * blockDim.x + threadIdx.x;
    if (e >= ET) return;
    int d = g_dst[e];
    float ev = expf(g_lg2[e] - g_mx2[d]);
    g_lg2[e] = ev;
    atomicAdd(&g_dn2[d], ev);
}

__global__ void k_agg2(float* __restrict__ out) {
    int t = blockIdx.x * blockDim.x + threadIdx.x;
    int e = t >> 4;                     // 16 threads per edge
    if (e >= ET) return;
    int f4 = t & 15;
    int s = g_src[e], d = g_dst[e];
    float alpha = g_lg2[e] / fmaxf(g_dn2[d], 1e-16f);
    float4 v = *(const float4*)&g_h2[(size_t)s * OUT + f4 * 4];
    red_add4(&out[(size_t)d * OUT + f4 * 4], v.x * alpha, v.y * alpha, v.z * alpha, v.w * alpha);
}

// ---------------- launch ----------------
extern "C" void kernel_launch(void* const* d_in, const int* in_sizes, int n_in,
                              void* d_out, int out_size) {
    const float* x     = (const float*)d_in[0];
    const int*   ei    = (const int*)d_in[1];   // int32 or int64 — detected on device
    const float* W1    = (const float*)d_in[2];
    const float* asrc1 = (const float*)d_in[3];
    const float* adst1 = (const float*)d_in[4];
    const float* b1    = (const float*)d_in[5];
    const float* W2    = (const float*)d_in[6];
    const float* asrc2 = (const float*)d_in[7];
    const float* adst2 = (const float*)d_in[8];
    const float* b2    = (const float*)d_in[9];
    float* out = (float*)d_out;

    float* h1;   cudaGetSymbolAddress((void**)&h1, g_h1);
    float* out1; cudaGetSymbolAddress((void**)&out1, g_out1);
    float* h2;   cudaGetSymbolAddress((void**)&h2, g_h2);

    const int T = 256;

    // index decode
    k_detect<<<1, 32>>>(ei);
    k_convert<<<(ET + T - 1) / T, T>>>(ei);

    // layer 1
    k_init1<<<(NN * F1 + T - 1) / T, T>>>(b1);
    gemm_kernel<128, 128, 16, 8, 8><<<dim3(F1 / 128, (NN + 127) / 128), 256>>>(x, W1, h1, NN, F1, INCH);
    k_al1<<<(NN * H1 + T - 1) / T, T>>>(asrc1, adst1);
    k_logit1<<<(ET + T - 1) / T, T>>>();
    k_exp1<<<(ET + T - 1) / T, T>>>();
    k_agg1<<<((size_t)ET * 32 + T - 1) / T, T>>>();
    k_elu<<<(NN * F1 + T - 1) / T, T>>>();

    // layer 2
    k_init2<<<(NN * OUT + T - 1) / T, T>>>(b2, out);
    gemm_kernel<128, 64, 16, 8, 4><<<dim3(OUT / 64, (NN + 127) / 128), 256>>>(out1, W2, h2, NN, OUT, F1);
    k_al2<<<(NN + T - 1) / T, T>>>(asrc2, adst2);
    k_logit2<<<(ET + T - 1) / T, T>>>();
    k_exp2<<<(ET + T - 1) / T, T>>>();
    k_agg2<<<((size_t)ET * 16 + T - 1) / T, T>>>(out);
}

// round 7
// speedup vs baseline: 1.5969x; 1.5969x over previous
#include <cuda_runtime.h>
#include <cstdint>
#include <math.h>

// Problem constants (fixed shapes from reference)
#define NN 50000
#define EE 800000
#define ET (EE + NN)   // edges + self loops
#define INCH 128
#define HID 64
#define H1 4
#define OUT 64
#define F1 (H1*HID)    // 256

// ---------------- scratch (device globals; no allocation allowed) ----------
__device__ __align__(16) float g_h1[(size_t)NN * F1];     // x @ W1
__device__ __align__(16) float g_out1[(size_t)NN * F1];   // agg1 out (+b1, ELU fused)
__device__ __align__(16) float g_h2[(size_t)NN * OUT];    // out1 @ W2
__device__ __align__(16) float g_als1[NN * H1];
__device__ __align__(16) float g_ald1[NN * H1];
__device__ __align__(16) float g_als2[NN];
__device__ __align__(16) float g_ald2[NN];
// edge decode + CSR
__device__ int g_src[ET];
__device__ int g_dst[ET];
__device__ int g_cnt[NN];      // in-degree
__device__ int g_start[NN];    // CSR row start (exclusive prefix of cnt)
__device__ int g_cur[NN];      // scatter cursor
__device__ int g_bsum[64];     // scan block sums
__device__ int g_csrc[ET];     // CSR: src node per slot, segmented by dst
__device__ int g_is64;

#define SCAN_B 49              // ceil(50000/1024)

__device__ __forceinline__ float lrelu(float x) { return x > 0.0f ? x : 0.2f * x; }

// ---------------- edge index dtype detection + conversion ----------------
__global__ void k_detect(const int* __restrict__ ei_raw) {
    if (blockIdx.x == 0 && threadIdx.x == 0) {
        int all0 = 1;
#pragma unroll
        for (int i = 1; i < 128; i += 2) all0 &= (ei_raw[i] == 0);
        g_is64 = all0;
    }
}

__global__ void k_convert(const int* __restrict__ ei_raw) {
    int e = blockIdx.x * blockDim.x + threadIdx.x;
    if (e >= ET) return;
    int s, d;
    if (e < EE) {
        if (g_is64) {
            const long long* p = (const long long*)ei_raw;
            s = (int)p[e]; d = (int)p[EE + e];
        } else {
            s = ei_raw[e]; d = ei_raw[EE + e];
        }
        s = min(max(s, 0), NN - 1);
        d = min(max(d, 0), NN - 1);
    } else {
        s = d = e - EE;
    }
    g_src[e] = s; g_dst[e] = d;
}

// ---------------- CSR build ----------------
__global__ void k_zero_cnt() {
    int i = blockIdx.x * blockDim.x + threadIdx.x;
    if (i < NN) g_cnt[i] = 0;
}

__global__ void k_hist() {
    int e = blockIdx.x * blockDim.x + threadIdx.x;
    if (e < ET) atomicAdd(&g_cnt[g_dst[e]], 1);
}

__global__ void k_scan1() {
    __shared__ int sm[1024];
    int tid = threadIdx.x;
    int i = blockIdx.x * 1024 + tid;
    int v = (i < NN) ? g_cnt[i] : 0;
    sm[tid] = v;
    __syncthreads();
#pragma unroll
    for (int off = 1; off < 1024; off <<= 1) {
        int t = (tid >= off) ? sm[tid - off] : 0;
        __syncthreads();
        sm[tid] += t;
        __syncthreads();
    }
    int incl = sm[tid];
    if (i < NN) g_start[i] = incl - v;           // local exclusive
    if (tid == 1023) g_bsum[blockIdx.x] = incl;  // block total
}

__global__ void k_scan2() {
    __shared__ int sm[64];
    int tid = threadIdx.x;
    sm[tid] = (tid < SCAN_B) ? g_bsum[tid] : 0;
    __syncthreads();
    if (tid == 0) {
        int run = 0;
        for (int i = 0; i < SCAN_B; i++) { int t = sm[i]; sm[i] = run; run += t; }
    }
    __syncthreads();
    if (tid < SCAN_B) g_bsum[tid] = sm[tid];
}

__global__ void k_scan3() {
    int i = blockIdx.x * 1024 + threadIdx.x;
    if (i < NN) {
        int st = g_start[i] + g_bsum[blockIdx.x];
        g_start[i] = st;
        g_cur[i] = st;
    }
}

__global__ void k_scatter() {
    int e = blockIdx.x * blockDim.x + threadIdx.x;
    if (e >= ET) return;
    int p = atomicAdd(&g_cur[g_dst[e]], 1);
    g_csrc[p] = g_src[e];
}

// ---------------- GEMM (fp32 SIMT, register tiled) ----------------
template<int BM, int BN, int BK, int TM, int TN>
__global__ void gemm_kernel(const float* __restrict__ A, const float* __restrict__ B,
                            float* __restrict__ C, int M, int N, int K) {
    __shared__ float As[BK][BM];
    __shared__ float Bs[BK][BN];
    constexpr int THREADS = (BM / TM) * (BN / TN);
    const int tid = threadIdx.x;
    const int tcol = tid % (BN / TN);
    const int trow = tid / (BN / TN);
    const int brow = blockIdx.y * BM;
    const int bcol = blockIdx.x * BN;

    float acc[TM][TN];
#pragma unroll
    for (int i = 0; i < TM; i++)
#pragma unroll
        for (int j = 0; j < TN; j++) acc[i][j] = 0.0f;

    for (int k0 = 0; k0 < K; k0 += BK) {
#pragma unroll
        for (int i = tid * 4; i < BM * BK; i += THREADS * 4) {
            int m = i / BK, kk = i % BK;
            float4 v = make_float4(0.f, 0.f, 0.f, 0.f);
            int gm = brow + m;
            if (gm < M) v = *(const float4*)&A[(size_t)gm * K + k0 + kk];
            As[kk + 0][m] = v.x; As[kk + 1][m] = v.y;
            As[kk + 2][m] = v.z; As[kk + 3][m] = v.w;
        }
#pragma unroll
        for (int i = tid * 4; i < BK * BN; i += THREADS * 4) {
            int kk = i / BN, n = i % BN;
            float4 v = *(const float4*)&B[(size_t)(k0 + kk) * N + bcol + n];
            *(float4*)&Bs[kk][n] = v;
        }
        __syncthreads();
#pragma unroll
        for (int kk = 0; kk < BK; kk++) {
            float ar[TM], br[TN];
#pragma unroll
            for (int i = 0; i < TM; i++) ar[i] = As[kk][trow * TM + i];
#pragma unroll
            for (int j = 0; j < TN; j++) br[j] = Bs[kk][tcol * TN + j];
#pragma unroll
            for (int i = 0; i < TM; i++)
#pragma unroll
                for (int j = 0; j < TN; j++) acc[i][j] += ar[i] * br[j];
        }
        __syncthreads();
    }
#pragma unroll
    for (int i = 0; i < TM; i++) {
        int gm = brow + trow * TM + i;
        if (gm >= M) continue;
#pragma unroll
        for (int j = 0; j < TN; j += 4) {
            float4 v = make_float4(acc[i][j], acc[i][j+1], acc[i][j+2], acc[i][j+3]);
            *(float4*)&C[(size_t)gm * N + bcol + tcol * TN + j] = v;
        }
    }
}

// ---------------- attention coefficients ----------------
__global__ void k_al1(const float* __restrict__ asrc, const float* __restrict__ adst) {
    int t = blockIdx.x * blockDim.x + threadIdx.x;   // node*4 + head
    if (t >= NN * H1) return;
    int n = t >> 2, h = t & 3;
    const float* hp = &g_h1[(size_t)n * F1 + h * HID];
    const float* ap = &asrc[h * HID];
    const float* bp = &adst[h * HID];
    float s = 0.f, d = 0.f;
#pragma unroll
    for (int i = 0; i < HID / 4; i++) {
        float4 hv = *(const float4*)&hp[i * 4];
        float4 av = *(const float4*)&ap[i * 4];
        float4 bv = *(const float4*)&bp[i * 4];
        s += hv.x * av.x + hv.y * av.y + hv.z * av.z + hv.w * av.w;
        d += hv.x * bv.x + hv.y * bv.y + hv.z * bv.z + hv.w * bv.w;
    }
    g_als1[t] = s; g_ald1[t] = d;
}

__global__ void k_al2(const float* __restrict__ asrc, const float* __restrict__ adst) {
    int n = blockIdx.x * blockDim.x + threadIdx.x;
    if (n >= NN) return;
    const float* hp = &g_h2[(size_t)n * OUT];
    float s = 0.f, d = 0.f;
#pragma unroll
    for (int i = 0; i < OUT / 4; i++) {
        float4 hv = *(const float4*)&hp[i * 4];
        float4 av = *(const float4*)&asrc[i * 4];
        float4 bv = *(const float4*)&adst[i * 4];
        s += hv.x * av.x + hv.y * av.y + hv.z * av.z + hv.w * av.w;
        d += hv.x * bv.x + hv.y * bv.y + hv.z * bv.z + hv.w * bv.w;
    }
    g_als2[n] = s; g_ald2[n] = d;
}

// ---------------- fused softmax + aggregate, layer 1 ----------------
// 64 threads per dst node (2 warps, each warp = 2 heads). Thread owns one
// float4 column. Leader lanes (0,16 of each warp) compute exp once per
// edge-head; shuffled to the other 15 lanes. No max-shift needed: logits are
// O(6) << 88, and alpha = e^l/sum(e^l) is shift-invariant.
__global__ void k_agg1_csr(const float* __restrict__ b1) {
    int node = blockIdx.x * 4 + (threadIdx.x >> 6);
    int g    = threadIdx.x & 63;    // float4 column 0..63
    int h    = g >> 4;              // head
    int lane = threadIdx.x & 31;
    int start = g_start[node];
    int deg   = g_cnt[node];
    float ald = g_ald1[node * 4 + h];
    bool leader = (lane & 15) == 0;

    float4 acc = make_float4(0.f, 0.f, 0.f, 0.f);
    float denom = 0.f;
    for (int j = 0; j < deg; j++) {
        int s = __ldg(&g_csrc[start + j]);
        float e = 0.f;
        if (leader) e = __expf(lrelu(g_als1[s * 4 + h] + ald));
        e = __shfl_sync(0xffffffffu, e, lane & 16);
        float4 v = *(const float4*)&g_h1[(size_t)s * F1 + g * 4];
        acc.x += e * v.x; acc.y += e * v.y; acc.z += e * v.z; acc.w += e * v.w;
        denom += e;
    }
    float inv = 1.0f / fmaxf(denom, 1e-16f);
    float4 bv = *(const float4*)&b1[g * 4];
    float4 r;
    r.x = acc.x * inv + bv.x;
    r.y = acc.y * inv + bv.y;
    r.z = acc.z * inv + bv.z;
    r.w = acc.w * inv + bv.w;
    // fused ELU
    r.x = r.x > 0.f ? r.x : expm1f(r.x);
    r.y = r.y > 0.f ? r.y : expm1f(r.y);
    r.z = r.z > 0.f ? r.z : expm1f(r.z);
    r.w = r.w > 0.f ? r.w : expm1f(r.w);
    *(float4*)&g_out1[(size_t)node * F1 + g * 4] = r;
}

// ---------------- fused softmax + aggregate, layer 2 ----------------
// 16 threads per dst node; 2 nodes per warp, so loop to the max degree of
// the pair and predicate the work to keep __shfl_sync converged.
__global__ void k_agg2_csr(const float* __restrict__ b2, float* __restrict__ out) {
    int node = blockIdx.x * 16 + (threadIdx.x >> 4);
    int c    = threadIdx.x & 15;    // float4 column 0..15
    int lane = threadIdx.x & 31;
    int start = g_start[node];
    int deg   = g_cnt[node];
    int mdeg  = max(deg, __shfl_xor_sync(0xffffffffu, deg, 16));
    float ald = g_ald2[node];
    bool leader = (lane & 15) == 0;

    float4 acc = make_float4(0.f, 0.f, 0.f, 0.f);
    float denom = 0.f;
    for (int j = 0; j < mdeg; j++) {
        int idx = start + min(j, deg - 1);      // deg >= 1 (self-loop)
        int s = __ldg(&g_csrc[idx]);
        float e = 0.f;
        if (leader && j < deg) e = __expf(lrelu(g_als2[s] + ald));
        e = __shfl_sync(0xffffffffu, e, lane & 16);
        float4 v = *(const float4*)&g_h2[(size_t)s * OUT + c * 4];
        acc.x += e * v.x; acc.y += e * v.y; acc.z += e * v.z; acc.w += e * v.w;
        denom += e;
    }
    float inv = 1.0f / fmaxf(denom, 1e-16f);
    float4 bv = *(const float4*)&b2[c * 4];
    float4 r;
    r.x = acc.x * inv + bv.x;
    r.y = acc.y * inv + bv.y;
    r.z = acc.z * inv + bv.z;
    r.w = acc.w * inv + bv.w;
    *(float4*)&out[(size_t)node * OUT + c * 4] = r;
}

// ---------------- launch ----------------
extern "C" void kernel_launch(void* const* d_in, const int* in_sizes, int n_in,
                              void* d_out, int out_size) {
    const float* x     = (const float*)d_in[0];
    const int*   ei    = (const int*)d_in[1];   // int32 or int64, detected on device
    const float* W1    = (const float*)d_in[2];
    const float* asrc1 = (const float*)d_in[3];
    const float* adst1 = (const float*)d_in[4];
    const float* b1    = (const float*)d_in[5];
    const float* W2    = (const float*)d_in[6];
    const float* asrc2 = (const float*)d_in[7];
    const float* adst2 = (const float*)d_in[8];
    const float* b2    = (const float*)d_in[9];
    float* out = (float*)d_out;

    float* h1;   cudaGetSymbolAddress((void**)&h1, g_h1);
    float* out1; cudaGetSymbolAddress((void**)&out1, g_out1);
    float* h2;   cudaGetSymbolAddress((void**)&h2, g_h2);

    const int T = 256;

    // edge decode + CSR build (shared by both layers)
    k_detect<<<1, 32>>>(ei);
    k_convert<<<(ET + T - 1) / T, T>>>(ei);
    k_zero_cnt<<<(NN + 1023) / 1024, 1024>>>();
    k_hist<<<(ET + T - 1) / T, T>>>();
    k_scan1<<<SCAN_B, 1024>>>();
    k_scan2<<<1, 64>>>();
    k_scan3<<<SCAN_B, 1024>>>();
    k_scatter<<<(ET + T - 1) / T, T>>>();

    // layer 1
    gemm_kernel<128, 128, 16, 8, 8><<<dim3(F1 / 128, (NN + 127) / 128), 256>>>(x, W1, h1, NN, F1, INCH);
    k_al1<<<(NN * H1 + T - 1) / T, T>>>(asrc1, adst1);
    k_agg1_csr<<<NN / 4, 256>>>(b1);

    // layer 2
    gemm_kernel<128, 64, 16, 8, 4><<<dim3(OUT / 64, (NN + 127) / 128), 256>>>(out1, W2, h2, NN, OUT, F1);
    k_al2<<<(NN + T - 1) / T, T>>>(asrc2, adst2);
    k_agg2_csr<<<NN / 16, 256>>>(b2, out);
}

// round 8
// speedup vs baseline: 1.7309x; 1.0839x over previous
#include <cuda_runtime.h>
#include <cstdint>
#include <math.h>

// Problem constants (fixed shapes from reference)
#define NN 50000
#define EE 800000
#define ET (EE + NN)   // edges + self loops
#define INCH 128
#define HID 64
#define H1 4
#define OUT 64
#define F1 (H1*HID)    // 256

// ---------------- scratch (device globals; no allocation allowed) ----------
__device__ __align__(16) float g_h1[(size_t)NN * F1];     // x @ W1
__device__ __align__(16) float g_out1[(size_t)NN * F1];   // agg1 out (+b1, ELU fused)
__device__ __align__(16) float g_h2[(size_t)NN * OUT];    // out1 @ W2
__device__ __align__(16) float g_als1[NN * H1];
__device__ __align__(16) float g_ald1[NN * H1];
__device__ __align__(16) float g_als2[NN];
__device__ __align__(16) float g_ald2[NN];
// edge decode + CSR
__device__ int g_src[ET];
__device__ int g_dst[ET];
__device__ int g_cnt[NN];      // in-degree
__device__ int g_start[NN];    // CSR row start
__device__ int g_cur[NN];      // scatter cursor
__device__ int g_bsum[64];     // scan block sums
__device__ int g_csrc[ET];     // CSR: src per slot, segmented by dst
__device__ int g_is64;

#define SCAN_B 49              // ceil(50000/1024)

__device__ __forceinline__ float lrelu(float x) { return x > 0.0f ? x : 0.2f * x; }

// ---------------- tf32 helpers ----------------
__device__ __forceinline__ uint32_t f2tf32(float x) {
    uint32_t r;
    asm("cvt.rna.tf32.f32 %0, %1;" : "=r"(r) : "f"(x));
    return r;
}

__device__ __forceinline__ void mma_tf32(float* c, const uint32_t* a, const uint32_t* b) {
    asm volatile(
        "mma.sync.aligned.m16n8k8.row.col.f32.tf32.tf32.f32 "
        "{%0,%1,%2,%3}, {%4,%5,%6,%7}, {%8,%9}, {%0,%1,%2,%3};"
        : "+f"(c[0]), "+f"(c[1]), "+f"(c[2]), "+f"(c[3])
        : "r"(a[0]), "r"(a[1]), "r"(a[2]), "r"(a[3]), "r"(b[0]), "r"(b[1]));
}

// ---------------- edge index dtype detection ----------------
__global__ void k_detect(const int* __restrict__ ei_raw) {
    if (blockIdx.x == 0 && threadIdx.x == 0) {
        int all0 = 1;
#pragma unroll
        for (int i = 1; i < 128; i += 2) all0 &= (ei_raw[i] == 0);
        g_is64 = all0;
    }
    // also zero the histogram (grid covers NN)
    int i = blockIdx.x * blockDim.x + threadIdx.x;
    if (i < NN) g_cnt[i] = 0;
}

// convert + clamp + histogram in one pass over edge_index
__global__ void k_convert_hist(const int* __restrict__ ei_raw) {
    int e = blockIdx.x * blockDim.x + threadIdx.x;
    if (e >= ET) return;
    int s, d;
    if (e < EE) {
        if (g_is64) {
            const long long* p = (const long long*)ei_raw;
            s = (int)p[e]; d = (int)p[EE + e];
        } else {
            s = ei_raw[e]; d = ei_raw[EE + e];
        }
        s = min(max(s, 0), NN - 1);
        d = min(max(d, 0), NN - 1);
    } else {
        s = d = e - EE;
    }
    g_src[e] = s; g_dst[e] = d;
    atomicAdd(&g_cnt[d], 1);
}

// ---------------- CSR build ----------------
__global__ void k_scan1() {
    __shared__ int sm[1024];
    int tid = threadIdx.x;
    int i = blockIdx.x * 1024 + tid;
    int v = (i < NN) ? g_cnt[i] : 0;
    sm[tid] = v;
    __syncthreads();
#pragma unroll
    for (int off = 1; off < 1024; off <<= 1) {
        int t = (tid >= off) ? sm[tid - off] : 0;
        __syncthreads();
        sm[tid] += t;
        __syncthreads();
    }
    int incl = sm[tid];
    if (i < NN) g_start[i] = incl - v;
    if (tid == 1023) g_bsum[blockIdx.x] = incl;
}

__global__ void k_scan2() {
    __shared__ int sm[64];
    int tid = threadIdx.x;
    sm[tid] = (tid < SCAN_B) ? g_bsum[tid] : 0;
    __syncthreads();
    if (tid == 0) {
        int run = 0;
        for (int i = 0; i < SCAN_B; i++) { int t = sm[i]; sm[i] = run; run += t; }
    }
    __syncthreads();
    if (tid < SCAN_B) g_bsum[tid] = sm[tid];
}

__global__ void k_scan3() {
    int i = blockIdx.x * 1024 + threadIdx.x;
    if (i < NN) {
        int st = g_start[i] + g_bsum[blockIdx.x];
        g_start[i] = st;
        g_cur[i] = st;
    }
}

__global__ void k_scatter() {
    int e = blockIdx.x * blockDim.x + threadIdx.x;
    if (e >= ET) return;
    int p = atomicAdd(&g_cur[g_dst[e]], 1);
    g_csrc[p] = g_src[e];
}

// ---------------- 3xTF32 tensor-core GEMM ----------------
// BM=128, BN=64, BK=16, 256 threads = 8 warps (4x2 warp grid), warp tile 32x32.
// Each fp32 operand is split a = hi + lo (both tf32); D accumulates
// hi*hi + hi*lo + lo*hi in fp32 => ~2^-21 effective precision.
#define TBM 128
#define TBN 64
#define TBK 16
#define A_STR (TBK + 1)   // 17
#define B_STR (TBN + 4)   // 68

__global__ void __launch_bounds__(256) gemm_tf32(
    const float* __restrict__ A, const float* __restrict__ B, float* __restrict__ C,
    int M, int N, int K
) {
    __shared__ float As_hi[TBM][A_STR], As_lo[TBM][A_STR];
    __shared__ float Bs_hi[TBK][B_STR], Bs_lo[TBK][B_STR];

    const int tid    = threadIdx.x;
    const int lane   = tid & 31;
    const int warp   = tid >> 5;
    const int warp_m = warp >> 1;     // 0..3
    const int warp_n = warp & 1;      // 0..1
    const int brow   = blockIdx.y * TBM;
    const int bcol   = blockIdx.x * TBN;
    const int grp    = lane >> 2;     // 0..7
    const int thr4   = lane & 3;      // 0..3

    float c[2][4][4];
#pragma unroll
    for (int mi = 0; mi < 2; mi++)
#pragma unroll
        for (int ni = 0; ni < 4; ni++)
#pragma unroll
            for (int r = 0; r < 4; r++) c[mi][ni][r] = 0.0f;

    for (int kt = 0; kt < K; kt += TBK) {
        // load A tile 128x16 (512 float4, 2 per thread), split hi/lo
#pragma unroll
        for (int p = 0; p < 2; p++) {
            int i = tid + p * 256;
            int r = i >> 2, c4 = (i & 3) * 4;
            float4 v = make_float4(0.f, 0.f, 0.f, 0.f);
            if (brow + r < M) v = *(const float4*)&A[(size_t)(brow + r) * K + kt + c4];
            uint32_t hx = f2tf32(v.x), hy = f2tf32(v.y), hz = f2tf32(v.z), hw = f2tf32(v.w);
            As_hi[r][c4+0] = __uint_as_float(hx);
            As_hi[r][c4+1] = __uint_as_float(hy);
            As_hi[r][c4+2] = __uint_as_float(hz);
            As_hi[r][c4+3] = __uint_as_float(hw);
            As_lo[r][c4+0] = __uint_as_float(f2tf32(v.x - __uint_as_float(hx)));
            As_lo[r][c4+1] = __uint_as_float(f2tf32(v.y - __uint_as_float(hy)));
            As_lo[r][c4+2] = __uint_as_float(f2tf32(v.z - __uint_as_float(hz)));
            As_lo[r][c4+3] = __uint_as_float(f2tf32(v.w - __uint_as_float(hw)));
        }
        // load B tile 16x64 (256 float4, 1 per thread), split hi/lo
        {
            int r = tid >> 4, c4 = (tid & 15) * 4;
            float4 v = *(const float4*)&B[(size_t)(kt + r) * N + bcol + c4];
            uint32_t hx = f2tf32(v.x), hy = f2tf32(v.y), hz = f2tf32(v.z), hw = f2tf32(v.w);
            Bs_hi[r][c4+0] = __uint_as_float(hx);
            Bs_hi[r][c4+1] = __uint_as_float(hy);
            Bs_hi[r][c4+2] = __uint_as_float(hz);
            Bs_hi[r][c4+3] = __uint_as_float(hw);
            Bs_lo[r][c4+0] = __uint_as_float(f2tf32(v.x - __uint_as_float(hx)));
            Bs_lo[r][c4+1] = __uint_as_float(f2tf32(v.y - __uint_as_float(hy)));
            Bs_lo[r][c4+2] = __uint_as_float(f2tf32(v.z - __uint_as_float(hz)));
            Bs_lo[r][c4+3] = __uint_as_float(f2tf32(v.w - __uint_as_float(hw)));
        }
        __syncthreads();

#pragma unroll
        for (int ks = 0; ks < TBK / 8; ks++) {
            const int k0 = ks * 8;
            uint32_t a_hi[2][4], a_lo[2][4];
#pragma unroll
            for (int mi = 0; mi < 2; mi++) {
                int r0 = warp_m * 32 + mi * 16 + grp;
                int cc = k0 + thr4;
                a_hi[mi][0] = __float_as_uint(As_hi[r0    ][cc    ]);
                a_hi[mi][1] = __float_as_uint(As_hi[r0 + 8][cc    ]);
                a_hi[mi][2] = __float_as_uint(As_hi[r0    ][cc + 4]);
                a_hi[mi][3] = __float_as_uint(As_hi[r0 + 8][cc + 4]);
                a_lo[mi][0] = __float_as_uint(As_lo[r0    ][cc    ]);
                a_lo[mi][1] = __float_as_uint(As_lo[r0 + 8][cc    ]);
                a_lo[mi][2] = __float_as_uint(As_lo[r0    ][cc + 4]);
                a_lo[mi][3] = __float_as_uint(As_lo[r0 + 8][cc + 4]);
            }
            uint32_t b_hi[4][2], b_lo[4][2];
#pragma unroll
            for (int ni = 0; ni < 4; ni++) {
                int kk = k0 + thr4;
                int nn = warp_n * 32 + ni * 8 + grp;
                b_hi[ni][0] = __float_as_uint(Bs_hi[kk    ][nn]);
                b_hi[ni][1] = __float_as_uint(Bs_hi[kk + 4][nn]);
                b_lo[ni][0] = __float_as_uint(Bs_lo[kk    ][nn]);
                b_lo[ni][1] = __float_as_uint(Bs_lo[kk + 4][nn]);
            }
#pragma unroll
            for (int mi = 0; mi < 2; mi++)
#pragma unroll
                for (int ni = 0; ni < 4; ni++) {
                    mma_tf32(c[mi][ni], a_hi[mi], b_hi[ni]);
                    mma_tf32(c[mi][ni], a_hi[mi], b_lo[ni]);
                    mma_tf32(c[mi][ni], a_lo[mi], b_hi[ni]);
                }
        }
        __syncthreads();
    }

    // epilogue
#pragma unroll
    for (int mi = 0; mi < 2; mi++) {
        int r0 = brow + warp_m * 32 + mi * 16 + grp;
#pragma unroll
        for (int ni = 0; ni < 4; ni++) {
            int cc = bcol + warp_n * 32 + ni * 8 + 2 * thr4;
            if (r0 < M)
                *(float2*)&C[(size_t)r0 * N + cc] = make_float2(c[mi][ni][0], c[mi][ni][1]);
            if (r0 + 8 < M)
                *(float2*)&C[(size_t)(r0 + 8) * N + cc] = make_float2(c[mi][ni][2], c[mi][ni][3]);
        }
    }
}

// ---------------- attention coefficients ----------------
__global__ void k_al1(const float* __restrict__ asrc, const float* __restrict__ adst) {
    int t = blockIdx.x * blockDim.x + threadIdx.x;   // node*4 + head
    if (t >= NN * H1) return;
    int n = t >> 2, h = t & 3;
    const float* hp = &g_h1[(size_t)n * F1 + h * HID];
    const float* ap = &asrc[h * HID];
    const float* bp = &adst[h * HID];
    float s = 0.f, d = 0.f;
#pragma unroll
    for (int i = 0; i < HID / 4; i++) {
        float4 hv = *(const float4*)&hp[i * 4];
        float4 av = *(const float4*)&ap[i * 4];
        float4 bv = *(const float4*)&bp[i * 4];
        s += hv.x * av.x + hv.y * av.y + hv.z * av.z + hv.w * av.w;
        d += hv.x * bv.x + hv.y * bv.y + hv.z * bv.z + hv.w * bv.w;
    }
    g_als1[t] = s; g_ald1[t] = d;
}

__global__ void k_al2(const float* __restrict__ asrc, const float* __restrict__ adst) {
    int n = blockIdx.x * blockDim.x + threadIdx.x;
    if (n >= NN) return;
    const float* hp = &g_h2[(size_t)n * OUT];
    float s = 0.f, d = 0.f;
#pragma unroll
    for (int i = 0; i < OUT / 4; i++) {
        float4 hv = *(const float4*)&hp[i * 4];
        float4 av = *(const float4*)&asrc[i * 4];
        float4 bv = *(const float4*)&adst[i * 4];
        s += hv.x * av.x + hv.y * av.y + hv.z * av.z + hv.w * av.w;
        d += hv.x * bv.x + hv.y * bv.y + hv.z * bv.z + hv.w * bv.w;
    }
    g_als2[n] = s; g_ald2[n] = d;
}

// ---------------- fused softmax + aggregate, layer 1 ----------------
__global__ void k_agg1_csr(const float* __restrict__ b1) {
    int node = blockIdx.x * 4 + (threadIdx.x >> 6);
    int g    = threadIdx.x & 63;    // float4 column 0..63
    int h    = g >> 4;              // head
    int lane = threadIdx.x & 31;
    int start = g_start[node];
    int deg   = g_cnt[node];
    float ald = g_ald1[node * 4 + h];
    bool leader = (lane & 15) == 0;

    float4 acc = make_float4(0.f, 0.f, 0.f, 0.f);
    float denom = 0.f;
    for (int j = 0; j < deg; j++) {
        int s = __ldg(&g_csrc[start + j]);
        float e = 0.f;
        if (leader) e = __expf(lrelu(g_als1[s * 4 + h] + ald));
        e = __shfl_sync(0xffffffffu, e, lane & 16);
        float4 v = *(const float4*)&g_h1[(size_t)s * F1 + g * 4];
        acc.x += e * v.x; acc.y += e * v.y; acc.z += e * v.z; acc.w += e * v.w;
        denom += e;
    }
    float inv = 1.0f / fmaxf(denom, 1e-16f);
    float4 bv = *(const float4*)&b1[g * 4];
    float4 r;
    r.x = acc.x * inv + bv.x;
    r.y = acc.y * inv + bv.y;
    r.z = acc.z * inv + bv.z;
    r.w = acc.w * inv + bv.w;
    r.x = r.x > 0.f ? r.x : expm1f(r.x);
    r.y = r.y > 0.f ? r.y : expm1f(r.y);
    r.z = r.z > 0.f ? r.z : expm1f(r.z);
    r.w = r.w > 0.f ? r.w : expm1f(r.w);
    *(float4*)&g_out1[(size_t)node * F1 + g * 4] = r;
}

// ---------------- fused softmax + aggregate, layer 2 ----------------
__global__ void k_agg2_csr(const float* __restrict__ b2, float* __restrict__ out) {
    int node = blockIdx.x * 16 + (threadIdx.x >> 4);
    int c    = threadIdx.x & 15;    // float4 column 0..15
    int lane = threadIdx.x & 31;
    int start = g_start[node];
    int deg   = g_cnt[node];
    int mdeg  = max(deg, __shfl_xor_sync(0xffffffffu, deg, 16));
    float ald = g_ald2[node];
    bool leader = (lane & 15) == 0;

    float4 acc = make_float4(0.f, 0.f, 0.f, 0.f);
    float denom = 0.f;
    for (int j = 0; j < mdeg; j++) {
        int idx = start + min(j, deg - 1);
        int s = __ldg(&g_csrc[idx]);
        float e = 0.f;
        if (leader && j < deg) e = __expf(lrelu(g_als2[s] + ald));
        e = __shfl_sync(0xffffffffu, e, lane & 16);
        float4 v = *(const float4*)&g_h2[(size_t)s * OUT + c * 4];
        acc.x += e * v.x; acc.y += e * v.y; acc.z += e * v.z; acc.w += e * v.w;
        denom += e;
    }
    float inv = 1.0f / fmaxf(denom, 1e-16f);
    float4 bv = *(const float4*)&b2[c * 4];
    float4 r;
    r.x = acc.x * inv + bv.x;
    r.y = acc.y * inv + bv.y;
    r.z = acc.z * inv + bv.z;
    r.w = acc.w * inv + bv.w;
    *(float4*)&out[(size_t)node * OUT + c * 4] = r;
}

// ---------------- launch ----------------
extern "C" void kernel_launch(void* const* d_in, const int* in_sizes, int n_in,
                              void* d_out, int out_size) {
    const float* x     = (const float*)d_in[0];
    const int*   ei    = (const int*)d_in[1];   // int32 or int64, detected on device
    const float* W1    = (const float*)d_in[2];
    const float* asrc1 = (const float*)d_in[3];
    const float* adst1 = (const float*)d_in[4];
    const float* b1    = (const float*)d_in[5];
    const float* W2    = (const float*)d_in[6];
    const float* asrc2 = (const float*)d_in[7];
    const float* adst2 = (const float*)d_in[8];
    const float* b2    = (const float*)d_in[9];
    float* out = (float*)d_out;

    float* h1;   cudaGetSymbolAddress((void**)&h1, g_h1);
    float* out1; cudaGetSymbolAddress((void**)&out1, g_out1);
    float* h2;   cudaGetSymbolAddress((void**)&h2, g_h2);

    const int T = 256;

    // edge decode + CSR build (shared by both layers)
    k_detect<<<(NN + 1023) / 1024, 1024>>>(ei);
    k_convert_hist<<<(ET + T - 1) / T, T>>>(ei);
    k_scan1<<<SCAN_B, 1024>>>();
    k_scan2<<<1, 64>>>();
    k_scan3<<<SCAN_B, 1024>>>();
    k_scatter<<<(ET + T - 1) / T, T>>>();

    // layer 1
    gemm_tf32<<<dim3(F1 / TBN, (NN + TBM - 1) / TBM), 256>>>(x, W1, h1, NN, F1, INCH);
    k_al1<<<(NN * H1 + T - 1) / T, T>>>(asrc1, adst1);
    k_agg1_csr<<<NN / 4, 256>>>(b1);

    // layer 2
    gemm_tf32<<<dim3(OUT / TBN, (NN + TBM - 1) / TBM), 256>>>(out1, W2, h2, NN, OUT, F1);
    k_al2<<<(NN + T - 1) / T, T>>>(asrc2, adst2);
    k_agg2_csr<<<NN / 16, 256>>>(b2, out);
}